// round 2
// baseline (speedup 1.0000x reference)
#include <cuda_runtime.h>
#include <cuda_bf16.h>

// Dilate (zero-insertion upsample) with stride (2,2):
//   in : (16, 64, 256, 256) fp32
//   out: (16, 64, 512, 512) fp32, out[b,c,2i,2j] = in[b,c,i,j], rest 0.
//
// Uniform-work version: each thread owns one input float4 (16B) and writes
// the corresponding 32B of the even output row (data interleaved with zeros)
// plus the 32B directly below in the odd output row (all zeros).
// Per thread: 1x LDG.128 + 4x STG.128, no divergence.
// Traffic: 268MB read + 1.074GB write = the exact floor.

#ifndef DIL_THREADS
#define DIL_THREADS 256
#endif

__global__ void __launch_bounds__(DIL_THREADS)
Dilate_35708358099161_kernel(const float4* __restrict__ in4,
                             float4* __restrict__ out4)
{
    // total threads = 16*64*256*256/4 = 16,777,216 (grid sized exactly)
    unsigned int t = blockIdx.x * DIL_THREADS + threadIdx.x;

    // input row = 256 floats = 64 float4; input float4 index == t
    unsigned int cin = t & 63u;          // float4 index within input row
    unsigned int row = t >> 6;           // global input-row index
    unsigned int hin = row & 255u;       // input row within image
    unsigned int bc  = row >> 8;         // image index, 0..1023

    // streaming load (read-once)
    float4 x = __ldcs(&in4[t]);

    // even output row base, in float4 units:
    //   bc*512*128 + (2*hin)*128 + 2*cin
    unsigned int e = (bc << 16) + (hin << 8) + (cin << 1);

    const float4 z = make_float4(0.f, 0.f, 0.f, 0.f);

    // even row: interleave data with zeros
    __stcs(&out4[e],     make_float4(x.x, 0.f, x.y, 0.f));
    __stcs(&out4[e + 1], make_float4(x.z, 0.f, x.w, 0.f));
    // odd row directly below: all zeros (+128 float4 = +512 floats)
    __stcs(&out4[e + 128], z);
    __stcs(&out4[e + 129], z);
}

extern "C" void kernel_launch(void* const* d_in, const int* in_sizes, int n_in,
                              void* d_out, int out_size)
{
    const float4* in4 = (const float4*)d_in[0];
    float4* out4 = (float4*)d_out;

    // threads = in elements / 4 = out_size / 16
    const unsigned int nthreads = (unsigned int)(out_size / 16);
    const unsigned int blocks = nthreads / DIL_THREADS;  // exact: 65,536

    Dilate_35708358099161_kernel<<<blocks, DIL_THREADS>>>(in4, out4);
}

// round 3
// speedup vs baseline: 1.0522x; 1.0522x over previous
#include <cuda_runtime.h>
#include <cuda_bf16.h>

// Dilate (zero-insertion upsample) with stride (2,2):
//   in : (16, 64, 256, 256) fp32
//   out: (16, 64, 512, 512) fp32, out[b,c,2i,2j] = in[b,c,i,j], rest 0.
//
// R1 layout (one output float4 per thread, warp-contiguous stores) +
// ILP x2 (each warp owns 64 consecutive float4 of one output row; lane
// handles offsets lane and lane+32) + streaming cache hints.
// Traffic: 268MB read + 1.074GB write = the exact floor.

#ifndef DIL_THREADS
#define DIL_THREADS 256
#endif

__global__ void __launch_bounds__(DIL_THREADS)
Dilate_35708358099161_kernel(const float2* __restrict__ in2,
                             float4* __restrict__ out4)
{
    unsigned int tid  = blockIdx.x * DIL_THREADS + threadIdx.x;
    unsigned int warp = tid >> 5;
    unsigned int lane = tid & 31u;

    // each warp owns 64 consecutive float4 (1KB) within one output row
    unsigned int v0 = (warp << 6) + lane;   // lane's first float4
    unsigned int v1 = v0 + 32u;             // lane's second float4

    // 128 float4 per out row; a 64-aligned chunk never crosses a row
    unsigned int row = v0 >> 7;             // global out-row index
    unsigned int h   = row & 511u;          // out row within image

    const float4 z = make_float4(0.f, 0.f, 0.f, 0.f);

    if (h & 1u) {
        __stcs(&out4[v0], z);
        __stcs(&out4[v1], z);
    } else {
        unsigned int bc   = row >> 9;       // image index, 0..1023
        unsigned int hin  = h >> 1;         // input row, 0..255
        unsigned int base = (bc << 15) + (hin << 7);  // float2 units

        // two independent 8B loads, each warp-coalesced (256B)
        float2 a = __ldcs(&in2[base + (v0 & 127u)]);
        float2 b = __ldcs(&in2[base + (v1 & 127u)]);

        __stcs(&out4[v0], make_float4(a.x, 0.f, a.y, 0.f));
        __stcs(&out4[v1], make_float4(b.x, 0.f, b.y, 0.f));
    }
}

extern "C" void kernel_launch(void* const* d_in, const int* in_sizes, int n_in,
                              void* d_out, int out_size)
{
    const float2* in2 = (const float2*)d_in[0];
    float4* out4 = (float4*)d_out;

    // out_size = 268,435,456 floats -> 67,108,864 float4 -> /2 per thread
    const unsigned int nthreads = (unsigned int)(out_size / 8);
    const unsigned int blocks = nthreads / DIL_THREADS;  // exact: 131,072

    Dilate_35708358099161_kernel<<<blocks, DIL_THREADS>>>(in2, out4);
}